// round 1
// baseline (speedup 1.0000x reference)
#include <cuda_runtime.h>

#define NN 8192
#define FF 256
#define CHUNKS 256
#define LCH 32            // NN / CHUNKS
#define RANK_SEGS 4
#define RANK_TILE 2048    // NN / RANK_SEGS

// ---------------- scratch (device globals; no allocations allowed) ----------
__device__ float g_s[NN];
__device__ float g_t[NN];
__device__ float g_c[NN];        // s + b3
__device__ float g_diag[NN];
__device__ unsigned long long g_key[NN];
__device__ int   g_rp[RANK_SEGS * NN];
__device__ float g_tsorted[NN];
__device__ int   g_perm[NN];
__device__ float g_G[NN * FF];
__device__ float g_M[NN * FF];
__device__ float g_P0[(NN + 1) * FF];
__device__ float g_P1[(NN + 1) * FF];
__device__ float g_cs0[CHUNKS * FF];
__device__ float g_cs1[CHUNKS * FF];

__device__ __forceinline__ float leaky_f(float z) { return z >= 0.f ? z : 0.1f * z; }

// ---------------- kernel 1: s, t, c, diag, sortable keys --------------------
// one warp per row; 8 warps per block
__global__ __launch_bounds__(256) void k_st(const float* __restrict__ x,
                                            const float* __restrict__ W3,
                                            const float* __restrict__ b3)
{
    int warp = threadIdx.x >> 5;
    int lane = threadIdx.x & 31;
    int i = blockIdx.x * 8 + warp;
    const float* xr = x + (size_t)i * FF;
    float as = 0.f, at = 0.f;
#pragma unroll
    for (int f = lane; f < FF; f += 32) {
        float xv = xr[f];
        as += xv * W3[f];
        at += xv * W3[FF + f];
    }
#pragma unroll
    for (int o = 16; o > 0; o >>= 1) {
        as += __shfl_down_sync(0xFFFFFFFFu, as, o);
        at += __shfl_down_sync(0xFFFFFFFFu, at, o);
    }
    if (lane == 0) {
        float b = b3[0];
        g_s[i] = as;
        g_t[i] = at;
        g_c[i] = as + b;
        g_diag[i] = leaky_f(as + at + b);
        // order-preserving uint mapping of float, tie-broken by index
        unsigned u = __float_as_uint(at);
        u = (u & 0x80000000u) ? ~u : (u | 0x80000000u);
        g_key[i] = ((unsigned long long)u << 13) | (unsigned)i;
    }
}

// ---------------- kernel 2a/2b: counting sort (rank) ------------------------
__global__ __launch_bounds__(256) void k_rankp()
{
    __shared__ unsigned long long tile[RANK_TILE];
    int j = blockIdx.x * 256 + threadIdx.x;
    unsigned long long kj = g_key[j];
    int base = blockIdx.y * RANK_TILE;
    for (int m = threadIdx.x; m < RANK_TILE; m += 256) tile[m] = g_key[base + m];
    __syncthreads();
    int cnt = 0;
#pragma unroll 16
    for (int m = 0; m < RANK_TILE; ++m) cnt += (tile[m] < kj) ? 1 : 0;
    g_rp[blockIdx.y * NN + j] = cnt;
}

__global__ __launch_bounds__(256) void k_scatter()
{
    int j = blockIdx.x * 256 + threadIdx.x;
    int rank = g_rp[j] + g_rp[NN + j] + g_rp[2 * NN + j] + g_rp[3 * NN + j];
    g_tsorted[rank] = g_t[j];
    g_perm[rank] = j;
}

// ---------------- GEMM: C = leaky(A[M,K] @ B[N,K]^T + bias) (+resid) --------
// M=8192, N=256, K=256.  BM=BN=64, BK=32, 256 threads, 4x4 micro-tile.
template <bool RESID>
__global__ __launch_bounds__(256) void k_gemm(const float* __restrict__ A,
                                              const float* __restrict__ B,
                                              const float* __restrict__ bias,
                                              const float* __restrict__ resid,
                                              float* __restrict__ C)
{
    __shared__ float As[32][68];
    __shared__ float Bs[32][68];
    int bm = blockIdx.x * 64;
    int bn = blockIdx.y * 64;
    int tid = threadIdx.x;
    int tx = tid & 15;
    int ty = tid >> 4;
    float acc[4][4] = {};

    for (int kt = 0; kt < FF; kt += 32) {
#pragma unroll
        for (int l = 0; l < 2; ++l) {
            int e = tid + l * 256;
            int row = e >> 3;
            int kl = (e & 7) * 4;
            float4 va = *(const float4*)(A + (size_t)(bm + row) * FF + kt + kl);
            As[kl + 0][row] = va.x; As[kl + 1][row] = va.y;
            As[kl + 2][row] = va.z; As[kl + 3][row] = va.w;
            float4 vb = *(const float4*)(B + (size_t)(bn + row) * FF + kt + kl);
            Bs[kl + 0][row] = vb.x; Bs[kl + 1][row] = vb.y;
            Bs[kl + 2][row] = vb.z; Bs[kl + 3][row] = vb.w;
        }
        __syncthreads();
#pragma unroll
        for (int kk = 0; kk < 32; ++kk) {
            float4 a = *(const float4*)&As[kk][ty * 4];
            float4 b = *(const float4*)&Bs[kk][tx * 4];
            float ar[4] = {a.x, a.y, a.z, a.w};
            float br[4] = {b.x, b.y, b.z, b.w};
#pragma unroll
            for (int r = 0; r < 4; ++r)
#pragma unroll
                for (int c = 0; c < 4; ++c) acc[r][c] += ar[r] * br[c];
        }
        __syncthreads();
    }

#pragma unroll
    for (int r = 0; r < 4; ++r) {
        int row = bm + ty * 4 + r;
#pragma unroll
        for (int c = 0; c < 4; ++c) {
            int col = bn + tx * 4 + c;
            float v = leaky_f(acc[r][c] + bias[col]);
            if (RESID) v += resid[(size_t)row * FF + col];
            C[(size_t)row * FF + col] = v;
        }
    }
}

// ---------------- prefix sums over sorted order ------------------------------
__global__ __launch_bounds__(256) void k_chunksum()
{
    int c = blockIdx.x;
    int k = threadIdx.x;
    float a0 = 0.f, a1 = 0.f;
    int base = c * LCH;
#pragma unroll 4
    for (int r = 0; r < LCH; ++r) {
        int m = base + r;
        int j = g_perm[m];
        float g = g_G[(size_t)j * FF + k];
        a0 += g;
        a1 += g_tsorted[m] * g;
    }
    g_cs0[c * FF + k] = a0;
    g_cs1[c * FF + k] = a1;
}

__global__ __launch_bounds__(256) void k_scan()
{
    int k = threadIdx.x;
    float r0 = 0.f, r1 = 0.f;
#pragma unroll 8
    for (int c = 0; c < CHUNKS; ++c) {
        float v0 = g_cs0[c * FF + k];
        float v1 = g_cs1[c * FF + k];
        g_cs0[c * FF + k] = r0;
        g_cs1[c * FF + k] = r1;
        r0 += v0;
        r1 += v1;
    }
    g_P0[(size_t)NN * FF + k] = r0;   // Gtot
    g_P1[(size_t)NN * FF + k] = r1;   // TGtot
}

__global__ __launch_bounds__(256) void k_prefix()
{
    int c = blockIdx.x;
    int k = threadIdx.x;
    float r0 = g_cs0[c * FF + k];
    float r1 = g_cs1[c * FF + k];
    int base = c * LCH;
#pragma unroll 4
    for (int r = 0; r < LCH; ++r) {
        int m = base + r;
        size_t off = (size_t)m * FF + k;
        g_P0[off] = r0;
        g_P1[off] = r1;
        int j = g_perm[m];
        float g = g_G[(size_t)j * FF + k];
        r0 += g;
        r1 += g_tsorted[m] * g;
    }
}

// ---------------- build M ----------------------------------------------------
__global__ __launch_bounds__(256) void k_buildM()
{
    __shared__ int smi;
    __shared__ float sci, sdi;
    int i = blockIdx.x;
    if (threadIdx.x == 0) {
        float ci = g_c[i];
        float keyv = -ci;
        int lo = 0, hi = NN;
        while (lo < hi) {
            int mid = (lo + hi) >> 1;
            if (g_tsorted[mid] < keyv) lo = mid + 1; else hi = mid;
        }
        smi = lo;
        sci = ci;
        sdi = g_diag[i];
    }
    __syncthreads();
    int k = threadIdx.x;
    int m = smi;
    float ci = sci, di = sdi;
    float G0 = g_P0[(size_t)NN * FF + k];
    float G1 = g_P1[(size_t)NN * FF + k];
    float p0 = g_P0[(size_t)m * FF + k];
    float p1 = g_P1[(size_t)m * FF + k];
    float lin  = ci * G0 + G1;
    float absr = ci * (G0 - 2.f * p0) + (G1 - 2.f * p1);
    float rowv = 0.55f * lin + 0.45f * absr;
    float Mik = (rowv - di * g_G[(size_t)i * FF + k]) * (1.0f / (float)(NN - 1));
    g_M[(size_t)i * FF + k] = Mik;
}

// ---------------- launch -----------------------------------------------------
extern "C" void kernel_launch(void* const* d_in, const int* in_sizes, int n_in,
                              void* d_out, int out_size)
{
    const float* x  = (const float*)d_in[0];
    const float* W3 = (const float*)d_in[1];
    const float* b3 = (const float*)d_in[2];
    const float* W6 = (const float*)d_in[3];
    const float* b6 = (const float*)d_in[4];
    const float* W5 = (const float*)d_in[5];
    const float* b5 = (const float*)d_in[6];
    float* out = (float*)d_out;

    void *pG = nullptr, *pM = nullptr;
    cudaGetSymbolAddress(&pG, g_G);
    cudaGetSymbolAddress(&pM, g_M);

    k_st<<<NN / 8, 256>>>(x, W3, b3);
    k_rankp<<<dim3(NN / 256, RANK_SEGS), 256>>>();
    k_scatter<<<NN / 256, 256>>>();
    k_gemm<false><<<dim3(NN / 64, FF / 64), 256>>>(x, W6, b6, nullptr, (float*)pG);
    k_chunksum<<<CHUNKS, 256>>>();
    k_scan<<<1, 256>>>();
    k_prefix<<<CHUNKS, 256>>>();
    k_buildM<<<NN, 256>>>();
    k_gemm<true><<<dim3(NN / 64, FF / 64), 256>>>((const float*)pM, W5, b5, x, out);
}

// round 2
// speedup vs baseline: 1.3728x; 1.3728x over previous
#include <cuda_runtime.h>
#include <cuda_bf16.h>

#define NN 8192
#define FF 256
#define CHUNKS 256
#define LCH 32            // NN / CHUNKS
#define RANK_SEGS 4
#define RANK_TILE 2048    // NN / RANK_SEGS

#define BM 128
#define BN 64
#define BK 32
#define ASTR 40                                   // bf16 elems per smem row (pad)
#define STAGE_ELEMS (2*BM*ASTR + 2*BN*ASTR)       // 15360 bf16 per stage
#define SMEM_BYTES (2 * STAGE_ELEMS * 2)          // 61440 bytes

using bf16 = __nv_bfloat16;

// ---------------- scratch (device globals; no allocations allowed) ----------
__device__ float g_s[NN];
__device__ float g_t[NN];
__device__ float g_c[NN];
__device__ float g_diag[NN];
__device__ unsigned long long g_key[NN];
__device__ int   g_rp[RANK_SEGS * NN];
__device__ float g_tsorted[NN];
__device__ int   g_perm[NN];
__device__ int   g_mi[NN];
__device__ float g_G[NN * FF];
__device__ float g_P0[(NN + 1) * FF];
__device__ float g_P1[(NN + 1) * FF];
__device__ float g_cs0[CHUNKS * FF];
__device__ float g_cs1[CHUNKS * FF];
// bf16 split operands
__device__ bf16 g_xh[NN * FF];
__device__ bf16 g_xl[NN * FF];
__device__ bf16 g_Mh[NN * FF];
__device__ bf16 g_Ml[NN * FF];
__device__ bf16 g_W6h[FF * FF];
__device__ bf16 g_W6l[FF * FF];
__device__ bf16 g_W5h[FF * FF];
__device__ bf16 g_W5l[FF * FF];

__device__ __forceinline__ float leaky_f(float z) { return fmaxf(z, 0.1f * z); }

__device__ __forceinline__ void split2(float v, bf16& h, bf16& l) {
    h = __float2bfloat16(v);
    l = __float2bfloat16(v - __bfloat162float(h));
}

// ---------------- kernel 1: s, t, c, diag, sortable keys --------------------
__global__ __launch_bounds__(256) void k_st(const float* __restrict__ x,
                                            const float* __restrict__ W3,
                                            const float* __restrict__ b3)
{
    int warp = threadIdx.x >> 5;
    int lane = threadIdx.x & 31;
    int i = blockIdx.x * 8 + warp;
    const float* xr = x + (size_t)i * FF;
    float as = 0.f, at = 0.f;
#pragma unroll
    for (int f = lane; f < FF; f += 32) {
        float xv = xr[f];
        as += xv * W3[f];
        at += xv * W3[FF + f];
    }
#pragma unroll
    for (int o = 16; o > 0; o >>= 1) {
        as += __shfl_down_sync(0xFFFFFFFFu, as, o);
        at += __shfl_down_sync(0xFFFFFFFFu, at, o);
    }
    if (lane == 0) {
        float b = b3[0];
        g_s[i] = as;
        g_t[i] = at;
        g_c[i] = as + b;
        g_diag[i] = leaky_f(as + at + b);
        unsigned u = __float_as_uint(at);
        u = (u & 0x80000000u) ? ~u : (u | 0x80000000u);
        g_key[i] = ((unsigned long long)u << 13) | (unsigned)i;
    }
}

// ---------------- counting-sort rank ----------------------------------------
__global__ __launch_bounds__(256) void k_rankp()
{
    __shared__ unsigned long long tile[RANK_TILE];
    int j = blockIdx.x * 256 + threadIdx.x;
    unsigned long long kj = g_key[j];
    int base = blockIdx.y * RANK_TILE;
    for (int m = threadIdx.x; m < RANK_TILE; m += 256) tile[m] = g_key[base + m];
    __syncthreads();
    int cnt = 0;
#pragma unroll 16
    for (int m = 0; m < RANK_TILE; ++m) cnt += (tile[m] < kj) ? 1 : 0;
    g_rp[blockIdx.y * NN + j] = cnt;
}

__global__ __launch_bounds__(256) void k_scatter()
{
    int j = blockIdx.x * 256 + threadIdx.x;
    int rank = g_rp[j] + g_rp[NN + j] + g_rp[2 * NN + j] + g_rp[3 * NN + j];
    g_tsorted[rank] = g_t[j];
    g_perm[rank] = j;
}

// ---------------- fp32 -> bf16 hi/lo conversion ------------------------------
__global__ __launch_bounds__(256) void k_conv(const float* __restrict__ s,
                                              bf16* __restrict__ h,
                                              bf16* __restrict__ l, int n4)
{
    int idx = blockIdx.x * 256 + threadIdx.x;
    if (idx >= n4) return;
    float4 v = ((const float4*)s)[idx];
    bf16 h0, h1, h2, h3, l0, l1, l2, l3;
    split2(v.x, h0, l0); split2(v.y, h1, l1);
    split2(v.z, h2, l2); split2(v.w, h3, l3);
    unsigned ph0 = (unsigned)__bfloat16_as_ushort(h0) | ((unsigned)__bfloat16_as_ushort(h1) << 16);
    unsigned ph1 = (unsigned)__bfloat16_as_ushort(h2) | ((unsigned)__bfloat16_as_ushort(h3) << 16);
    unsigned pl0 = (unsigned)__bfloat16_as_ushort(l0) | ((unsigned)__bfloat16_as_ushort(l1) << 16);
    unsigned pl1 = (unsigned)__bfloat16_as_ushort(l2) | ((unsigned)__bfloat16_as_ushort(l3) << 16);
    ((uint2*)h)[idx] = make_uint2(ph0, ph1);
    ((uint2*)l)[idx] = make_uint2(pl0, pl1);
}

// ---------------- tensor-core GEMM (split bf16, 3 terms) ---------------------
__device__ __forceinline__ void mma16816(float c[4], const unsigned a[4], const unsigned b[2])
{
    asm volatile(
        "mma.sync.aligned.m16n8k16.row.col.f32.bf16.bf16.f32 "
        "{%0,%1,%2,%3}, {%4,%5,%6,%7}, {%8,%9}, {%0,%1,%2,%3};\n"
        : "+f"(c[0]), "+f"(c[1]), "+f"(c[2]), "+f"(c[3])
        : "r"(a[0]), "r"(a[1]), "r"(a[2]), "r"(a[3]), "r"(b[0]), "r"(b[1]));
}

#define CPA(dst, src) asm volatile("cp.async.cg.shared.global [%0], [%1], 16;\n" \
    :: "r"((unsigned)__cvta_generic_to_shared(dst)), "l"(src))

template <bool RESID>
__global__ __launch_bounds__(256) void k_gemm_t(
    const bf16* __restrict__ Agh, const bf16* __restrict__ Agl,
    const bf16* __restrict__ Bgh, const bf16* __restrict__ Bgl,
    const float* __restrict__ bias, const float* __restrict__ resid,
    float* __restrict__ C)
{
    extern __shared__ bf16 sm[];
    const int tid = threadIdx.x;
    const int bm = blockIdx.x * BM;
    const int bn = blockIdx.y * BN;
    const int lane = tid & 31;
    const int warp = tid >> 5;
    const int wm = warp & 3;
    const int wn = warp >> 2;
    const int qr = lane >> 2;
    const int qc = (lane & 3) * 2;

    float acc[2][4][4] = {};

    auto load_stage = [&](int kt, int buf) {
        bf16* Ah = sm + buf * STAGE_ELEMS;
        bf16* Al = Ah + BM * ASTR;
        bf16* Bh = Al + BM * ASTR;
        bf16* Bl = Bh + BN * ASTR;
#pragma unroll
        for (int e = tid; e < BM * 4; e += 256) {
            int row = e >> 2, seg = (e & 3) << 3;
            size_t so = (size_t)(bm + row) * FF + kt + seg;
            CPA(Ah + row * ASTR + seg, Agh + so);
            CPA(Al + row * ASTR + seg, Agl + so);
        }
        {
            int e = tid;            // BN*4 == 256 exactly
            int row = e >> 2, seg = (e & 3) << 3;
            size_t so = (size_t)(bn + row) * FF + kt + seg;
            CPA(Bh + row * ASTR + seg, Bgh + so);
            CPA(Bl + row * ASTR + seg, Bgl + so);
        }
        asm volatile("cp.async.commit_group;\n" ::);
    };

    load_stage(0, 0);
    int buf = 0;
    for (int kt = 0; kt < FF; kt += BK) {
        if (kt + BK < FF) {
            load_stage(kt + BK, buf ^ 1);
            asm volatile("cp.async.wait_group 1;\n" ::);
        } else {
            asm volatile("cp.async.wait_group 0;\n" ::);
        }
        __syncthreads();

        const bf16* Ah = sm + buf * STAGE_ELEMS;
        const bf16* Al = Ah + BM * ASTR;
        const bf16* Bh = Al + BM * ASTR;
        const bf16* Bl = Bh + BN * ASTR;

#pragma unroll
        for (int ks = 0; ks < BK; ks += 16) {
            unsigned ah[2][4], al[2][4], bh[4][2], bl[4][2];
#pragma unroll
            for (int mi = 0; mi < 2; mi++) {
                int r = wm * 32 + mi * 16 + qr;
                const bf16* p = Ah + r * ASTR + ks + qc;
                ah[mi][0] = *(const unsigned*)p;
                ah[mi][2] = *(const unsigned*)(p + 8);
                ah[mi][1] = *(const unsigned*)(p + 8 * ASTR);
                ah[mi][3] = *(const unsigned*)(p + 8 * ASTR + 8);
                const bf16* q = Al + r * ASTR + ks + qc;
                al[mi][0] = *(const unsigned*)q;
                al[mi][2] = *(const unsigned*)(q + 8);
                al[mi][1] = *(const unsigned*)(q + 8 * ASTR);
                al[mi][3] = *(const unsigned*)(q + 8 * ASTR + 8);
            }
#pragma unroll
            for (int ni = 0; ni < 4; ni++) {
                int n = wn * 32 + ni * 8 + qr;
                const bf16* p = Bh + n * ASTR + ks + qc;
                bh[ni][0] = *(const unsigned*)p;
                bh[ni][1] = *(const unsigned*)(p + 8);
                const bf16* q = Bl + n * ASTR + ks + qc;
                bl[ni][0] = *(const unsigned*)q;
                bl[ni][1] = *(const unsigned*)(q + 8);
            }
#pragma unroll
            for (int mi = 0; mi < 2; mi++)
#pragma unroll
                for (int ni = 0; ni < 4; ni++) {
                    mma16816(acc[mi][ni], ah[mi], bh[ni]);
                    mma16816(acc[mi][ni], ah[mi], bl[ni]);
                    mma16816(acc[mi][ni], al[mi], bh[ni]);
                }
        }
        __syncthreads();
        buf ^= 1;
    }

    // epilogue
#pragma unroll
    for (int mi = 0; mi < 2; mi++) {
        int r = bm + wm * 32 + mi * 16 + qr;
#pragma unroll
        for (int ni = 0; ni < 4; ni++) {
            int cl = bn + wn * 32 + ni * 8 + qc;
            float b0 = bias[cl], b1 = bias[cl + 1];
            float v0 = leaky_f(acc[mi][ni][0] + b0);
            float v1 = leaky_f(acc[mi][ni][1] + b1);
            float v2 = leaky_f(acc[mi][ni][2] + b0);
            float v3 = leaky_f(acc[mi][ni][3] + b1);
            size_t o0 = (size_t)r * FF + cl;
            size_t o8 = (size_t)(r + 8) * FF + cl;
            if (RESID) {
                v0 += resid[o0]; v1 += resid[o0 + 1];
                v2 += resid[o8]; v3 += resid[o8 + 1];
            }
            *(float2*)(C + o0) = make_float2(v0, v1);
            *(float2*)(C + o8) = make_float2(v2, v3);
        }
    }
}

// ---------------- prefix sums over sorted order ------------------------------
__global__ __launch_bounds__(256) void k_chunksum()
{
    int c = blockIdx.x;
    int k = threadIdx.x;
    float a0 = 0.f, a1 = 0.f;
    int base = c * LCH;
#pragma unroll 4
    for (int r = 0; r < LCH; ++r) {
        int m = base + r;
        int j = g_perm[m];
        float g = g_G[(size_t)j * FF + k];
        a0 += g;
        a1 += g_tsorted[m] * g;
    }
    g_cs0[c * FF + k] = a0;
    g_cs1[c * FF + k] = a1;
}

__global__ __launch_bounds__(256) void k_scan()
{
    int k = threadIdx.x;
    float r0 = 0.f, r1 = 0.f;
#pragma unroll 8
    for (int c = 0; c < CHUNKS; ++c) {
        float v0 = g_cs0[c * FF + k];
        float v1 = g_cs1[c * FF + k];
        g_cs0[c * FF + k] = r0;
        g_cs1[c * FF + k] = r1;
        r0 += v0;
        r1 += v1;
    }
    g_P0[(size_t)NN * FF + k] = r0;
    g_P1[(size_t)NN * FF + k] = r1;
}

__global__ __launch_bounds__(256) void k_prefix()
{
    int c = blockIdx.x;
    int k = threadIdx.x;
    float r0 = g_cs0[c * FF + k];
    float r1 = g_cs1[c * FF + k];
    int base = c * LCH;
#pragma unroll 4
    for (int r = 0; r < LCH; ++r) {
        int m = base + r;
        size_t off = (size_t)m * FF + k;
        g_P0[off] = r0;
        g_P1[off] = r1;
        int j = g_perm[m];
        float g = g_G[(size_t)j * FF + k];
        r0 += g;
        r1 += g_tsorted[m] * g;
    }
}

// ---------------- binary search (t_sorted staged in smem) --------------------
__global__ __launch_bounds__(256) void k_search()
{
    __shared__ float ts[NN];
    for (int m = threadIdx.x; m < NN; m += 256) ts[m] = g_tsorted[m];
    __syncthreads();
    int i = blockIdx.x * 256 + threadIdx.x;
    float keyv = -g_c[i];
    int lo = 0, hi = NN;
    while (lo < hi) {
        int mid = (lo + hi) >> 1;
        if (ts[mid] < keyv) lo = mid + 1; else hi = mid;
    }
    g_mi[i] = lo;
}

// ---------------- build M (writes bf16 split directly) -----------------------
__global__ __launch_bounds__(256) void k_buildM()
{
    int i = blockIdx.x;
    int k = threadIdx.x;
    int m = g_mi[i];
    float ci = g_c[i];
    float di = g_diag[i];
    float G0 = g_P0[(size_t)NN * FF + k];
    float G1 = g_P1[(size_t)NN * FF + k];
    float p0 = g_P0[(size_t)m * FF + k];
    float p1 = g_P1[(size_t)m * FF + k];
    float lin  = ci * G0 + G1;
    float absr = ci * (G0 - 2.f * p0) + (G1 - 2.f * p1);
    float rowv = 0.55f * lin + 0.45f * absr;
    float Mik = (rowv - di * g_G[(size_t)i * FF + k]) * (1.0f / (float)(NN - 1));
    bf16 h, l;
    split2(Mik, h, l);
    g_Mh[(size_t)i * FF + k] = h;
    g_Ml[(size_t)i * FF + k] = l;
}

// ---------------- launch -----------------------------------------------------
extern "C" void kernel_launch(void* const* d_in, const int* in_sizes, int n_in,
                              void* d_out, int out_size)
{
    const float* x  = (const float*)d_in[0];
    const float* W3 = (const float*)d_in[1];
    const float* b3 = (const float*)d_in[2];
    const float* W6 = (const float*)d_in[3];
    const float* b6 = (const float*)d_in[4];
    const float* W5 = (const float*)d_in[5];
    const float* b5 = (const float*)d_in[6];
    float* out = (float*)d_out;

    void *pG, *pxh, *pxl, *pW6h, *pW6l, *pW5h, *pW5l, *pMh, *pMl;
    cudaGetSymbolAddress(&pG, g_G);
    cudaGetSymbolAddress(&pxh, g_xh);
    cudaGetSymbolAddress(&pxl, g_xl);
    cudaGetSymbolAddress(&pW6h, g_W6h);
    cudaGetSymbolAddress(&pW6l, g_W6l);
    cudaGetSymbolAddress(&pW5h, g_W5h);
    cudaGetSymbolAddress(&pW5l, g_W5l);
    cudaGetSymbolAddress(&pMh, g_Mh);
    cudaGetSymbolAddress(&pMl, g_Ml);

    cudaFuncSetAttribute(k_gemm_t<false>, cudaFuncAttributeMaxDynamicSharedMemorySize, SMEM_BYTES);
    cudaFuncSetAttribute(k_gemm_t<true>,  cudaFuncAttributeMaxDynamicSharedMemorySize, SMEM_BYTES);

    dim3 ggrid(NN / BM, FF / BN);

    k_conv<<<(NN * FF / 4 + 255) / 256, 256>>>(x, (bf16*)pxh, (bf16*)pxl, NN * FF / 4);
    k_conv<<<(FF * FF / 4 + 255) / 256, 256>>>(W6, (bf16*)pW6h, (bf16*)pW6l, FF * FF / 4);
    k_conv<<<(FF * FF / 4 + 255) / 256, 256>>>(W5, (bf16*)pW5h, (bf16*)pW5l, FF * FF / 4);
    k_st<<<NN / 8, 256>>>(x, W3, b3);
    k_rankp<<<dim3(NN / 256, RANK_SEGS), 256>>>();
    k_scatter<<<NN / 256, 256>>>();
    k_gemm_t<false><<<ggrid, 256, SMEM_BYTES>>>((const bf16*)pxh, (const bf16*)pxl,
                                                (const bf16*)pW6h, (const bf16*)pW6l,
                                                b6, nullptr, (float*)pG);
    k_chunksum<<<CHUNKS, 256>>>();
    k_scan<<<1, 256>>>();
    k_prefix<<<CHUNKS, 256>>>();
    k_search<<<NN / 256, 256>>>();
    k_buildM<<<NN, 256>>>();
    k_gemm_t<true><<<ggrid, 256, SMEM_BYTES>>>((const bf16*)pMh, (const bf16*)pMl,
                                               (const bf16*)pW5h, (const bf16*)pW5l,
                                               b5, x, out);
}

// round 3
// speedup vs baseline: 1.4882x; 1.0841x over previous
#include <cuda_runtime.h>
#include <cuda_bf16.h>

#define NN 8192
#define FF 256
#define CHUNKS 256
#define LCH 32            // NN / CHUNKS
#define RANK_SEGS 4
#define RANK_TILE 2048    // NN / RANK_SEGS

#define BM 128
#define BN 64
#define BK 32
#define ASTR 40                                   // bf16 elems per smem row (pad)
#define STAGE_ELEMS (2*BM*ASTR + 2*BN*ASTR)       // 15360 bf16 per stage
#define SMEM_BYTES (2 * STAGE_ELEMS * 2)          // 61440 bytes

using bf16 = __nv_bfloat16;

// ---------------- scratch (device globals; no allocations allowed) ----------
__device__ float g_t[NN];
__device__ float g_c[NN];
__device__ float g_diag[NN];
__device__ unsigned long long g_key[NN];
__device__ int   g_rp[RANK_SEGS * NN];
__device__ float g_tsorted[NN];
__device__ int   g_perm[NN];
__device__ int   g_mi[NN];
__device__ float g_H[NN * FF];                 // H = G @ W5^T
__device__ float g_P0[(NN + 1) * FF];          // prefix of H rows (sorted order)
__device__ float g_P1[(NN + 1) * FF];          // prefix of t*H rows
__device__ float g_cs0[CHUNKS * FF];
__device__ float g_cs1[CHUNKS * FF];
// bf16 split operands
__device__ bf16 g_xh[NN * FF];
__device__ bf16 g_xl[NN * FF];
__device__ bf16 g_Gh[NN * FF];
__device__ bf16 g_Gl[NN * FF];
__device__ bf16 g_W6h[FF * FF];
__device__ bf16 g_W6l[FF * FF];
__device__ bf16 g_W5h[FF * FF];
__device__ bf16 g_W5l[FF * FF];

__device__ __forceinline__ float leaky_f(float z) { return fmaxf(z, 0.1f * z); }

__device__ __forceinline__ unsigned pack2(float a, float b, unsigned& lo) {
    bf16 ha = __float2bfloat16(a);
    bf16 hb = __float2bfloat16(b);
    bf16 la = __float2bfloat16(a - __bfloat162float(ha));
    bf16 lb = __float2bfloat16(b - __bfloat162float(hb));
    lo = (unsigned)__bfloat16_as_ushort(la) | ((unsigned)__bfloat16_as_ushort(lb) << 16);
    return (unsigned)__bfloat16_as_ushort(ha) | ((unsigned)__bfloat16_as_ushort(hb) << 16);
}

// ---------------- kernel 1: s,t,c,diag,keys + x bf16 split ------------------
__global__ __launch_bounds__(256) void k_st(const float* __restrict__ x,
                                            const float* __restrict__ W3,
                                            const float* __restrict__ b3,
                                            bf16* __restrict__ xh,
                                            bf16* __restrict__ xl)
{
    __shared__ float w[2 * FF];
    int tid = threadIdx.x;
    w[tid] = W3[tid];
    w[tid + 256] = W3[tid + 256];
    __syncthreads();

    int warp = tid >> 5;
    int lane = tid & 31;
    int i = blockIdx.x * 8 + warp;
    const float* xr = x + (size_t)i * FF + lane * 8;
    float4 v0 = *(const float4*)xr;
    float4 v1 = *(const float4*)(xr + 4);
    float vv[8] = {v0.x, v0.y, v0.z, v0.w, v1.x, v1.y, v1.z, v1.w};

    float as = 0.f, at = 0.f;
#pragma unroll
    for (int u = 0; u < 8; ++u) {
        as += vv[u] * w[lane * 8 + u];
        at += vv[u] * w[FF + lane * 8 + u];
    }
#pragma unroll
    for (int o = 16; o > 0; o >>= 1) {
        as += __shfl_down_sync(0xFFFFFFFFu, as, o);
        at += __shfl_down_sync(0xFFFFFFFFu, at, o);
    }

    // bf16 split of x
    unsigned hp[4], lp[4];
#pragma unroll
    for (int u = 0; u < 4; ++u) hp[u] = pack2(vv[2 * u], vv[2 * u + 1], lp[u]);
    size_t off = (size_t)i * FF + lane * 8;
    *(uint4*)(xh + off) = make_uint4(hp[0], hp[1], hp[2], hp[3]);
    *(uint4*)(xl + off) = make_uint4(lp[0], lp[1], lp[2], lp[3]);

    if (lane == 0) {
        float b = b3[0];
        g_t[i] = at;
        g_c[i] = as + b;
        g_diag[i] = leaky_f(as + at + b);
        unsigned u = __float_as_uint(at);
        u = (u & 0x80000000u) ? ~u : (u | 0x80000000u);
        g_key[i] = ((unsigned long long)u << 13) | (unsigned)i;
    }
}

// ---------------- counting-sort rank ----------------------------------------
__global__ __launch_bounds__(256) void k_rankp()
{
    __shared__ unsigned long long tile[RANK_TILE];
    int j = blockIdx.x * 256 + threadIdx.x;
    unsigned long long kj = g_key[j];
    int base = blockIdx.y * RANK_TILE;
    for (int m = threadIdx.x; m < RANK_TILE; m += 256) tile[m] = g_key[base + m];
    __syncthreads();
    int cnt = 0;
#pragma unroll 16
    for (int m = 0; m < RANK_TILE; ++m) cnt += (tile[m] < kj) ? 1 : 0;
    g_rp[blockIdx.y * NN + j] = cnt;
}

__global__ __launch_bounds__(256) void k_scatter()
{
    int j = blockIdx.x * 256 + threadIdx.x;
    int rank = g_rp[j] + g_rp[NN + j] + g_rp[2 * NN + j] + g_rp[3 * NN + j];
    g_tsorted[rank] = g_t[j];
    g_perm[rank] = j;
}

// ---------------- binary search (t_sorted staged in smem) --------------------
__global__ __launch_bounds__(256) void k_search()
{
    __shared__ float ts[NN];
    for (int m = threadIdx.x; m < NN; m += 256) ts[m] = g_tsorted[m];
    __syncthreads();
    int i = blockIdx.x * 256 + threadIdx.x;
    float keyv = -g_c[i];
    int lo = 0, hi = NN;
    while (lo < hi) {
        int mid = (lo + hi) >> 1;
        if (ts[mid] < keyv) lo = mid + 1; else hi = mid;
    }
    g_mi[i] = lo;
}

// ---------------- W6 + W5 fp32 -> bf16 hi/lo in one launch -------------------
__global__ __launch_bounds__(256) void k_convW(const float* __restrict__ W6,
                                               const float* __restrict__ W5)
{
    int idx = blockIdx.x * 256 + threadIdx.x;     // 0 .. 2*FF*FF/4-1
    const int half = FF * FF / 4;
    const float* src = (idx < half) ? W6 : W5;
    bf16* dh = (idx < half) ? g_W6h : g_W5h;
    bf16* dl = (idx < half) ? g_W6l : g_W5l;
    int e = (idx < half) ? idx : idx - half;
    float4 v = ((const float4*)src)[e];
    unsigned l0, l1, h0 = pack2(v.x, v.y, l0), h1 = pack2(v.z, v.w, l1);
    ((uint2*)dh)[e] = make_uint2(h0, h1);
    ((uint2*)dl)[e] = make_uint2(l0, l1);
}

// ---------------- tensor-core GEMM (split bf16, 3 terms) ---------------------
__device__ __forceinline__ void mma16816(float c[4], const unsigned a[4], const unsigned b[2])
{
    asm volatile(
        "mma.sync.aligned.m16n8k16.row.col.f32.bf16.bf16.f32 "
        "{%0,%1,%2,%3}, {%4,%5,%6,%7}, {%8,%9}, {%0,%1,%2,%3};\n"
        : "+f"(c[0]), "+f"(c[1]), "+f"(c[2]), "+f"(c[3])
        : "r"(a[0]), "r"(a[1]), "r"(a[2]), "r"(a[3]), "r"(b[0]), "r"(b[1]));
}

#define CPA(dst, src) asm volatile("cp.async.cg.shared.global [%0], [%1], 16;\n" \
    :: "r"((unsigned)__cvta_generic_to_shared(dst)), "l"(src))

// MODE 0: C = leaky(acc + bias) -> bf16 split (Ch, Cl)
// MODE 1: C = acc               -> fp32 (Cf)
template <int MODE>
__global__ __launch_bounds__(256) void k_gemm_t(
    const bf16* __restrict__ Agh, const bf16* __restrict__ Agl,
    const bf16* __restrict__ Bgh, const bf16* __restrict__ Bgl,
    const float* __restrict__ bias,
    bf16* __restrict__ Ch, bf16* __restrict__ Cl, float* __restrict__ Cf)
{
    extern __shared__ bf16 sm[];
    const int tid = threadIdx.x;
    const int bm = blockIdx.x * BM;
    const int bn = blockIdx.y * BN;
    const int lane = tid & 31;
    const int warp = tid >> 5;
    const int wm = warp & 3;
    const int wn = warp >> 2;
    const int qr = lane >> 2;
    const int qc = (lane & 3) * 2;

    float acc[2][4][4] = {};

    auto load_stage = [&](int kt, int buf) {
        bf16* Ah = sm + buf * STAGE_ELEMS;
        bf16* Al = Ah + BM * ASTR;
        bf16* Bh = Al + BM * ASTR;
        bf16* Bl = Bh + BN * ASTR;
#pragma unroll
        for (int e = tid; e < BM * 4; e += 256) {
            int row = e >> 2, seg = (e & 3) << 3;
            size_t so = (size_t)(bm + row) * FF + kt + seg;
            CPA(Ah + row * ASTR + seg, Agh + so);
            CPA(Al + row * ASTR + seg, Agl + so);
        }
        {
            int e = tid;            // BN*4 == 256 exactly
            int row = e >> 2, seg = (e & 3) << 3;
            size_t so = (size_t)(bn + row) * FF + kt + seg;
            CPA(Bh + row * ASTR + seg, Bgh + so);
            CPA(Bl + row * ASTR + seg, Bgl + so);
        }
        asm volatile("cp.async.commit_group;\n" ::);
    };

    load_stage(0, 0);
    int buf = 0;
    for (int kt = 0; kt < FF; kt += BK) {
        if (kt + BK < FF) {
            load_stage(kt + BK, buf ^ 1);
            asm volatile("cp.async.wait_group 1;\n" ::);
        } else {
            asm volatile("cp.async.wait_group 0;\n" ::);
        }
        __syncthreads();

        const bf16* Ah = sm + buf * STAGE_ELEMS;
        const bf16* Al = Ah + BM * ASTR;
        const bf16* Bh = Al + BM * ASTR;
        const bf16* Bl = Bh + BN * ASTR;

#pragma unroll
        for (int ks = 0; ks < BK; ks += 16) {
            unsigned ah[2][4], al[2][4], bh[4][2], bl[4][2];
#pragma unroll
            for (int mi = 0; mi < 2; mi++) {
                int r = wm * 32 + mi * 16 + qr;
                const bf16* p = Ah + r * ASTR + ks + qc;
                ah[mi][0] = *(const unsigned*)p;
                ah[mi][2] = *(const unsigned*)(p + 8);
                ah[mi][1] = *(const unsigned*)(p + 8 * ASTR);
                ah[mi][3] = *(const unsigned*)(p + 8 * ASTR + 8);
                const bf16* q = Al + r * ASTR + ks + qc;
                al[mi][0] = *(const unsigned*)q;
                al[mi][2] = *(const unsigned*)(q + 8);
                al[mi][1] = *(const unsigned*)(q + 8 * ASTR);
                al[mi][3] = *(const unsigned*)(q + 8 * ASTR + 8);
            }
#pragma unroll
            for (int ni = 0; ni < 4; ni++) {
                int n = wn * 32 + ni * 8 + qr;
                const bf16* p = Bh + n * ASTR + ks + qc;
                bh[ni][0] = *(const unsigned*)p;
                bh[ni][1] = *(const unsigned*)(p + 8);
                const bf16* q = Bl + n * ASTR + ks + qc;
                bl[ni][0] = *(const unsigned*)q;
                bl[ni][1] = *(const unsigned*)(q + 8);
            }
#pragma unroll
            for (int mi = 0; mi < 2; mi++)
#pragma unroll
                for (int ni = 0; ni < 4; ni++) {
                    mma16816(acc[mi][ni], ah[mi], bh[ni]);
                    mma16816(acc[mi][ni], ah[mi], bl[ni]);
                    mma16816(acc[mi][ni], al[mi], bh[ni]);
                }
        }
        __syncthreads();
        buf ^= 1;
    }

    // epilogue
#pragma unroll
    for (int mi = 0; mi < 2; mi++) {
        int r = bm + wm * 32 + mi * 16 + qr;
#pragma unroll
        for (int ni = 0; ni < 4; ni++) {
            int cl = bn + wn * 32 + ni * 8 + qc;
            size_t o0 = (size_t)r * FF + cl;
            size_t o8 = (size_t)(r + 8) * FF + cl;
            if (MODE == 0) {
                float b0 = bias[cl], b1 = bias[cl + 1];
                float v0 = leaky_f(acc[mi][ni][0] + b0);
                float v1 = leaky_f(acc[mi][ni][1] + b1);
                float v2 = leaky_f(acc[mi][ni][2] + b0);
                float v3 = leaky_f(acc[mi][ni][3] + b1);
                unsigned l01, l23;
                unsigned h01 = pack2(v0, v1, l01);
                unsigned h23 = pack2(v2, v3, l23);
                *(unsigned*)(Ch + o0) = h01;
                *(unsigned*)(Cl + o0) = l01;
                *(unsigned*)(Ch + o8) = h23;
                *(unsigned*)(Cl + o8) = l23;
            } else {
                *(float2*)(Cf + o0) = make_float2(acc[mi][ni][0], acc[mi][ni][1]);
                *(float2*)(Cf + o8) = make_float2(acc[mi][ni][2], acc[mi][ni][3]);
            }
        }
    }
}

// ---------------- prefix sums over sorted order (on H) -----------------------
__global__ __launch_bounds__(256) void k_chunksum()
{
    int c = blockIdx.x;
    int k = threadIdx.x;
    float a0 = 0.f, a1 = 0.f;
    int base = c * LCH;
#pragma unroll 4
    for (int r = 0; r < LCH; ++r) {
        int m = base + r;
        int j = g_perm[m];
        float h = g_H[(size_t)j * FF + k];
        a0 += h;
        a1 += g_tsorted[m] * h;
    }
    g_cs0[c * FF + k] = a0;
    g_cs1[c * FF + k] = a1;
}

__global__ __launch_bounds__(256) void k_scan()
{
    int k = threadIdx.x;
    float r0 = 0.f, r1 = 0.f;
#pragma unroll 8
    for (int c = 0; c < CHUNKS; ++c) {
        float v0 = g_cs0[c * FF + k];
        float v1 = g_cs1[c * FF + k];
        g_cs0[c * FF + k] = r0;
        g_cs1[c * FF + k] = r1;
        r0 += v0;
        r1 += v1;
    }
    g_P0[(size_t)NN * FF + k] = r0;   // H0 total
    g_P1[(size_t)NN * FF + k] = r1;   // H1 total
}

__global__ __launch_bounds__(256) void k_prefix()
{
    int c = blockIdx.x;
    int k = threadIdx.x;
    float r0 = g_cs0[c * FF + k];
    float r1 = g_cs1[c * FF + k];
    int base = c * LCH;
#pragma unroll 4
    for (int r = 0; r < LCH; ++r) {
        int m = base + r;
        size_t off = (size_t)m * FF + k;
        g_P0[off] = r0;
        g_P1[off] = r1;
        int j = g_perm[m];
        float h = g_H[(size_t)j * FF + k];
        r0 += h;
        r1 += g_tsorted[m] * h;
    }
}

// ---------------- output epilogue --------------------------------------------
// out[i,k] = leaky( (ci*H0 + H1 - 0.9*(ci*p0 + p1) - di*H[i,k])/(N-1) + b5[k] ) + x[i,k]
__global__ __launch_bounds__(256) void k_out(const float* __restrict__ x,
                                             const float* __restrict__ b5,
                                             float* __restrict__ out)
{
    int k = threadIdx.x;
    float u0 = g_P0[(size_t)NN * FF + k];
    float u1 = g_P1[(size_t)NN * FF + k];
    float bk = b5[k];
    const float inv = 1.0f / (float)(NN - 1);
#pragma unroll
    for (int r = 0; r < 4; ++r) {
        int i = blockIdx.x * 4 + r;
        int m = __ldg(&g_mi[i]);
        float ci = __ldg(&g_c[i]);
        float di = __ldg(&g_diag[i]);
        float p0 = g_P0[(size_t)m * FF + k];
        float p1 = g_P1[(size_t)m * FF + k];
        float h  = g_H[(size_t)i * FF + k];
        float val = (ci * u0 + u1 - 0.9f * (ci * p0 + p1) - di * h) * inv;
        out[(size_t)i * FF + k] = leaky_f(val + bk) + x[(size_t)i * FF + k];
    }
}

// ---------------- launch -----------------------------------------------------
extern "C" void kernel_launch(void* const* d_in, const int* in_sizes, int n_in,
                              void* d_out, int out_size)
{
    const float* x  = (const float*)d_in[0];
    const float* W3 = (const float*)d_in[1];
    const float* b3 = (const float*)d_in[2];
    const float* W6 = (const float*)d_in[3];
    const float* b6 = (const float*)d_in[4];
    const float* W5 = (const float*)d_in[5];
    const float* b5 = (const float*)d_in[6];
    float* out = (float*)d_out;

    void *pH, *pxh, *pxl, *pGh, *pGl, *pW6h, *pW6l, *pW5h, *pW5l;
    cudaGetSymbolAddress(&pH, g_H);
    cudaGetSymbolAddress(&pxh, g_xh);
    cudaGetSymbolAddress(&pxl, g_xl);
    cudaGetSymbolAddress(&pGh, g_Gh);
    cudaGetSymbolAddress(&pGl, g_Gl);
    cudaGetSymbolAddress(&pW6h, g_W6h);
    cudaGetSymbolAddress(&pW6l, g_W6l);
    cudaGetSymbolAddress(&pW5h, g_W5h);
    cudaGetSymbolAddress(&pW5l, g_W5l);

    cudaFuncSetAttribute(k_gemm_t<0>, cudaFuncAttributeMaxDynamicSharedMemorySize, SMEM_BYTES);
    cudaFuncSetAttribute(k_gemm_t<1>, cudaFuncAttributeMaxDynamicSharedMemorySize, SMEM_BYTES);

    dim3 ggrid(NN / BM, FF / BN);

    k_st<<<NN / 8, 256>>>(x, W3, b3, (bf16*)pxh, (bf16*)pxl);
    k_convW<<<(2 * FF * FF / 4) / 256, 256>>>(W6, W5);
    k_rankp<<<dim3(NN / 256, RANK_SEGS), 256>>>();
    k_scatter<<<NN / 256, 256>>>();
    k_search<<<NN / 256, 256>>>();
    k_gemm_t<0><<<ggrid, 256, SMEM_BYTES>>>((const bf16*)pxh, (const bf16*)pxl,
                                            (const bf16*)pW6h, (const bf16*)pW6l,
                                            b6, (bf16*)pGh, (bf16*)pGl, nullptr);
    k_gemm_t<1><<<ggrid, 256, SMEM_BYTES>>>((const bf16*)pGh, (const bf16*)pGl,
                                            (const bf16*)pW5h, (const bf16*)pW5l,
                                            nullptr, nullptr, nullptr, (float*)pH);
    k_chunksum<<<CHUNKS, 256>>>();
    k_scan<<<1, 256>>>();
    k_prefix<<<CHUNKS, 256>>>();
    k_out<<<NN / 4, 256>>>(x, b5, out);
}